// round 3
// baseline (speedup 1.0000x reference)
#include <cstdint>
#include <cuda_runtime.h>
#include <cuda_bf16.h>
#include <mma.h>

using namespace nvcuda;

#define OUT_F 2048
#define IN_F  2048
#define NNZ   209715

#define BM 128
#define BN 128
#define BK 16
#define LDS (BK + 4)   // 20 floats = 80B row stride, multiple of 16B (wmma ldm rule)

// Scratch: dense dequantized weight W[OUT_F][IN_F] (16 MB). Device global to
// satisfy the no-allocation rule.
__device__ float g_W[(size_t)OUT_F * IN_F];

// ---------------------------------------------------------------------------
// Kernel 1: dequantize int4 base into g_W.
// packed[o][j] holds two offset-by-8 nibbles: low -> col 2j, high -> col 2j+1.
// ---------------------------------------------------------------------------
__global__ void dequant_kernel(const int* __restrict__ packed,
                               const float* __restrict__ scales) {
    int idx = blockIdx.x * blockDim.x + threadIdx.x;       // over OUT_F * IN_F/2
    const int total = OUT_F * (IN_F / 2);
    if (idx >= total) return;
    int o = idx >> 10;                                     // IN_F/2 == 1024
    int p = packed[idx];
    float s = scales[o];
    float2 v;
    v.x = (float)((p & 0xF) - 8) * s;
    v.y = (float)(((p >> 4) & 0xF) - 8) * s;
    reinterpret_cast<float2*>(g_W)[idx] = v;
}

// ---------------------------------------------------------------------------
// Kernel 2: scatter COO residual (duplicate coords must accumulate -> atomicAdd)
// ---------------------------------------------------------------------------
__global__ void scatter_kernel(const float* __restrict__ vals,
                               const int* __restrict__ rows,
                               const int* __restrict__ cols) {
    int i = blockIdx.x * blockDim.x + threadIdx.x;
    if (i >= NNZ) return;
    atomicAdd(&g_W[(size_t)rows[i] * IN_F + cols[i]], vals[i]);
}

// ---------------------------------------------------------------------------
// Kernel 3: GEMM out[t,o] = sum_i x[t,i] * W[o,i], fp32 in/out, tf32 mma.
// Block tile 128x128, K-tile 16, double-buffered cp.async.
// 8 warps in a 2x4 grid; each warp computes a 64x32 tile via m16n16k8 wmma.
// ---------------------------------------------------------------------------
__device__ __forceinline__ void cpasync16(void* smem, const void* gmem) {
    unsigned s = (unsigned)__cvta_generic_to_shared(smem);
    asm volatile("cp.async.cg.shared.global [%0], [%1], 16;\n" :: "r"(s), "l"(gmem));
}

__device__ __forceinline__ void load_stage(float (*sA)[LDS], float (*sB)[LDS],
                                           const float* gA, const float* gB,
                                           int k0, int tid) {
    // tile = 128 rows x 16 cols fp32 = 512 float4; 256 threads -> 2 float4 each
    #pragma unroll
    for (int r = 0; r < 2; r++) {
        int f   = tid + 256 * r;
        int row = f >> 2;           // 4 float4 per row
        int c   = (f & 3) * 4;
        cpasync16(&sA[row][c], gA + (size_t)row * IN_F + k0 + c);
        cpasync16(&sB[row][c], gB + (size_t)row * IN_F + k0 + c);
    }
}

__global__ __launch_bounds__(256, 2)
void gemm_kernel(const float* __restrict__ x, float* __restrict__ out,
                 int tokens) {
    __shared__ float sA[2][BM][LDS];
    __shared__ float sB[2][BN][LDS];

    const int tid  = threadIdx.x;
    const int warp = tid >> 5;
    const int wm   = warp >> 2;     // 0..1 -> 64-row slice
    const int wn   = warp & 3;      // 0..3 -> 32-col slice

    const int m0 = blockIdx.y * BM;
    const int n0 = blockIdx.x * BN;

    const float* gA = x + (size_t)m0 * IN_F;
    const float* gB = g_W + (size_t)n0 * IN_F;   // W rows are output features

    wmma::fragment<wmma::accumulator, 16, 16, 8, float> acc[4][2];
    #pragma unroll
    for (int i = 0; i < 4; i++)
        #pragma unroll
        for (int j = 0; j < 2; j++)
            wmma::fill_fragment(acc[i][j], 0.0f);

    const int KT = IN_F / BK;       // 128

    load_stage(sA[0], sB[0], gA, gB, 0, tid);
    asm volatile("cp.async.commit_group;\n");

    for (int kt = 0; kt < KT; kt++) {
        const int cur = kt & 1;
        if (kt + 1 < KT) {
            load_stage(sA[cur ^ 1], sB[cur ^ 1], gA, gB, (kt + 1) * BK, tid);
            asm volatile("cp.async.commit_group;\n");
            asm volatile("cp.async.wait_group 1;\n");
        } else {
            asm volatile("cp.async.wait_group 0;\n");
        }
        __syncthreads();

        #pragma unroll
        for (int ks = 0; ks < 2; ks++) {
            const int kk = ks * 8;
            wmma::fragment<wmma::matrix_a, 16, 16, 8,
                           wmma::precision::tf32, wmma::row_major> af[4];
            wmma::fragment<wmma::matrix_b, 16, 16, 8,
                           wmma::precision::tf32, wmma::col_major> bf[2];
            #pragma unroll
            for (int i = 0; i < 4; i++) {
                wmma::load_matrix_sync(af[i], &sA[cur][wm * 64 + i * 16][kk], LDS);
                #pragma unroll
                for (int e = 0; e < af[i].num_elements; e++)
                    af[i].x[e] = wmma::__float_to_tf32(af[i].x[e]);
            }
            #pragma unroll
            for (int j = 0; j < 2; j++) {
                wmma::load_matrix_sync(bf[j], &sB[cur][wn * 32 + j * 16][kk], LDS);
                #pragma unroll
                for (int e = 0; e < bf[j].num_elements; e++)
                    bf[j].x[e] = wmma::__float_to_tf32(bf[j].x[e]);
            }
            #pragma unroll
            for (int i = 0; i < 4; i++)
                #pragma unroll
                for (int j = 0; j < 2; j++)
                    wmma::mma_sync(acc[i][j], af[i], bf[j], acc[i][j]);
        }
        __syncthreads();
    }

    #pragma unroll
    for (int i = 0; i < 4; i++)
        #pragma unroll
        for (int j = 0; j < 2; j++) {
            float* dst = out + (size_t)(m0 + wm * 64 + i * 16) * OUT_F
                             + n0 + wn * 32 + j * 16;
            wmma::store_matrix_sync(dst, acc[i][j], OUT_F, wmma::mem_row_major);
        }
}

// ---------------------------------------------------------------------------
// Launch: inputs per metadata order:
//   0: x            float32 [4,4096,2048]
//   1: base_packed  int32   [2048,1024]
//   2: scales       float32 [2048]
//   3: ortho_vals   float32 [209715]
//   4: ortho_rows   int32   [209715]
//   5: ortho_cols   int32   [209715]
// output: float32 [4,4096,2048] (tokens x OUT_F)
// ---------------------------------------------------------------------------
extern "C" void kernel_launch(void* const* d_in, const int* in_sizes, int n_in,
                              void* d_out, int out_size) {
    const float* x      = (const float*)d_in[0];
    const int*   packed = (const int*)  d_in[1];
    const float* scales = (const float*)d_in[2];
    const float* ovals  = (const float*)d_in[3];
    const int*   orows  = (const int*)  d_in[4];
    const int*   ocols  = (const int*)  d_in[5];
    float*       out    = (float*)d_out;

    const int tokens = in_sizes[0] / IN_F;   // 16384

    dequant_kernel<<<(OUT_F * (IN_F / 2) + 255) / 256, 256>>>(packed, scales);
    scatter_kernel<<<(NNZ + 255) / 256, 256>>>(ovals, orows, ocols);

    dim3 grid(OUT_F / BN, tokens / BM);
    gemm_kernel<<<grid, 256>>>(x, out, tokens);
}